// round 13
// baseline (speedup 1.0000x reference)
#include <cuda_runtime.h>
#include <cuda_fp16.h>
#include <math.h>
#include <stdint.h>

// ---------------------------------------------------------------------------
// Problem: x (2,2048,512); W1 (512,2048); W2 (2048,512); HEADS=8
// M = 4096 rows. Output = concat(k, v, out), each 4096*512 fp32.
// R12 (resubmit): GEMM warp tile 64x64 (4-warp CTA, 2x2) — halves smem
// traffic per FLOP (smem-BW was the binding wall at 16.4 FLOP/B vs the
// 16 FLOP/B crossbar balance). 4-stage cp.async ring kept. Attention
// unchanged from R11.
// ---------------------------------------------------------------------------
#define MROWS 4096
#define DMODEL 512
#define HID 2048
#define SEQ 2048
#define NHEADS 8
#define DHEAD 64

#define BM 128
#define BN 128
#define BKK 32
#define HSTRIDE 40      // gemm smem row stride in halves (80B, conflict-free)

// Scratch (device globals: allocation-free rule)
__device__ __align__(16) __half g_hh[3][(size_t)MROWS * HID];     // hidden fp16
__device__ __align__(16) __half g_xh[(size_t)MROWS * DMODEL];     // x fp16
__device__ __align__(16) __half g_w1t[3][(size_t)HID * DMODEL];
__device__ __align__(16) __half g_w2t[3][(size_t)DMODEL * HID];
__device__ __align__(16) __half g_qh[(size_t)MROWS * DMODEL];     // q*0.125 fp16
__device__ __align__(16) __half g_kh[(size_t)MROWS * DMODEL];     // k fp16 copy
__device__ __align__(16) __half g_vh[(size_t)MROWS * DMODEL];     // v fp16 copy

// ----------------------------- helpers -------------------------------------
__device__ __forceinline__ uint32_t smem_u32(const void* p) {
    uint32_t a;
    asm("{ .reg .u64 t; cvta.to.shared.u64 t, %1; cvt.u32.u64 %0, t; }" : "=r"(a) : "l"(p));
    return a;
}
__device__ __forceinline__ void cp16(uint32_t saddr, const void* g) {
    asm volatile("cp.async.cg.shared.global [%0], [%1], 16;" :: "r"(saddr), "l"(g));
}
__device__ __forceinline__ float gelu_f(float x) {
    float x3 = x * x * x;
    float t = tanhf(0.7978845608028654f * (x + 0.044715f * x3));
    return 0.5f * x * (1.0f + t);
}
__device__ __forceinline__ void mma_f16(float* c, const uint32_t* a, const uint32_t* b) {
    asm volatile(
        "mma.sync.aligned.m16n8k16.row.col.f32.f16.f16.f32 "
        "{%0,%1,%2,%3}, {%4,%5,%6,%7}, {%8,%9}, {%0,%1,%2,%3};"
        : "+f"(c[0]), "+f"(c[1]), "+f"(c[2]), "+f"(c[3])
        : "r"(a[0]), "r"(a[1]), "r"(a[2]), "r"(a[3]), "r"(b[0]), "r"(b[1]));
}
__device__ __forceinline__ void ldsm4(uint32_t* r, uint32_t addr) {
    asm volatile("ldmatrix.sync.aligned.m8n8.x4.shared.b16 {%0,%1,%2,%3}, [%4];"
        : "=r"(r[0]), "=r"(r[1]), "=r"(r[2]), "=r"(r[3]) : "r"(addr));
}
__device__ __forceinline__ void ldsm4t(uint32_t* r, uint32_t addr) {
    asm volatile("ldmatrix.sync.aligned.m8n8.x4.trans.shared.b16 {%0,%1,%2,%3}, [%4];"
        : "=r"(r[0]), "=r"(r[1]), "=r"(r[2]), "=r"(r[3]) : "r"(addr));
}
__device__ __forceinline__ uint32_t h2pack(float a, float b) {
    __half2 h = __floats2half2_rn(a, b);
    return *(uint32_t*)&h;
}

// ---------------------------------------------------------------------------
// Prepass: convert x to fp16
// ---------------------------------------------------------------------------
__global__ void cvt_x_kernel(const float* __restrict__ in, __half* __restrict__ out, int n4) {
    int i = blockIdx.x * blockDim.x + threadIdx.x;
    if (i < n4) {
        float4 v = ((const float4*)in)[i];
        __half2 h0 = __floats2half2_rn(v.x, v.y);
        __half2 h1 = __floats2half2_rn(v.z, v.w);
        ((uint2*)out)[i] = make_uint2(*(uint32_t*)&h0, *(uint32_t*)&h1);
    }
}

// ---------------------------------------------------------------------------
// Prepass: transpose weights to fp16. src R x C fp32 -> dst C x R fp16.
// ---------------------------------------------------------------------------
__global__ void transpose_h(const float* __restrict__ s0, const float* __restrict__ s1,
                            const float* __restrict__ s2,
                            __half* __restrict__ d0, __half* __restrict__ d1,
                            __half* __restrict__ d2, int R, int C) {
    __shared__ float tile[32][33];
    const int z = blockIdx.z;
    const float* src = (z == 0) ? s0 : (z == 1) ? s1 : s2;
    __half* dst = (z == 0) ? d0 : (z == 1) ? d1 : d2;
    int tx = threadIdx.x, ty = threadIdx.y;
    int bx = blockIdx.x, by = blockIdx.y;
#pragma unroll
    for (int j = 0; j < 4; j++) {
        int r = by * 32 + ty + j * 8;
        int c = bx * 32 + tx;
        tile[ty + j * 8][tx] = src[(size_t)r * C + c];
    }
    __syncthreads();
#pragma unroll
    for (int j = 0; j < 4; j++) {
        int dr = bx * 32 + ty + j * 8;
        int dc = by * 32 + tx;
        dst[(size_t)dr * R + dc] = __float2half_rn(tile[tx][ty + j * 8]);
    }
}

// ---------------------------------------------------------------------------
// fp16 tensor-core GEMM, 4-stage ring, 4 warps x (64x64) warp tiles.
// out = act(A[z] @ Bt[z]^T + b[z])
// mode per z (4 bits): bit0 gelu, bit1 fp32 out, bit2 fp16 out, bit3 *0.125.
// Smem: A[4][128*40h] | B[4][128*40h] = 80KB, 2 CTAs/SM.
// ---------------------------------------------------------------------------
#define GA_OFF(buf) ((buf) * 10240u)
#define GB_OFF(buf) (40960u + (buf) * 10240u)
#define SM_BYTES 81920

__global__ void __launch_bounds__(128, 2) gemm_mma(
    const __half* __restrict__ A0, const __half* __restrict__ A1, const __half* __restrict__ A2,
    const __half* __restrict__ B0, const __half* __restrict__ B1, const __half* __restrict__ B2,
    const float* __restrict__ bias0, const float* __restrict__ bias1, const float* __restrict__ bias2,
    float* __restrict__ C0, float* __restrict__ C1, float* __restrict__ C2,
    __half* __restrict__ H0, __half* __restrict__ H1, __half* __restrict__ H2,
    int N, int K, int actModes)
{
    extern __shared__ char smem[];
    const uint32_t sb = smem_u32(smem);

    const int z = blockIdx.z;
    const __half* A = (z == 0) ? A0 : (z == 1) ? A1 : A2;
    const __half* B = (z == 0) ? B0 : (z == 1) ? B1 : B2;
    const float* bias = (z == 0) ? bias0 : (z == 1) ? bias1 : bias2;
    float* C = (z == 0) ? C0 : (z == 1) ? C1 : C2;
    __half* H = (z == 0) ? H0 : (z == 1) ? H1 : H2;
    const int mode = (actModes >> (4 * z)) & 15;

    const int tid = threadIdx.x;
    const int wid = tid >> 5;
    const int lane = tid & 31;
    const int bm = blockIdx.y * BM;
    const int bn = blockIdx.x * BN;
    const int wm = (wid >> 1) * 64;     // 2x2 warp grid, 64x64 per warp
    const int wn = (wid & 1) * 64;

    const int lr = lane >> 2;
    const int lc = lane & 3;

    // Global-load mapping: 128 rows x 4 16B-chunks per operand; 4+4 per thread.
    const int grow = tid >> 2;          // 0..31 (+32 per j)
    const int gchunk = tid & 3;

    // ldmatrix lane offsets (bytes within operand tile).
    uint32_t aOff[4];
#pragma unroll
    for (int mt = 0; mt < 4; mt++)
        aOff[mt] = (uint32_t)(wm + mt * 16 + (lane & 15)) * (HSTRIDE * 2) + ((lane >> 4) << 4);
    uint32_t bOff[4];
#pragma unroll
    for (int j = 0; j < 4; j++)
        bOff[j] = (uint32_t)(wn + (2 * j + (lane >> 4)) * 8 + (lane & 7)) * (HSTRIDE * 2) + (((lane >> 3) & 1) << 4);

    float acc[4][8][4];
#pragma unroll
    for (int i = 0; i < 4; i++)
#pragma unroll
        for (int j = 0; j < 8; j++)
#pragma unroll
            for (int t = 0; t < 4; t++) acc[i][j][t] = 0.0f;

    auto loadTile = [&](int kc, int buf) {
#pragma unroll
        for (int j = 0; j < 4; j++) {
            int r = grow + 32 * j;
            cp16(sb + GA_OFF(buf) + (uint32_t)r * (HSTRIDE * 2) + gchunk * 16,
                 A + (size_t)(bm + r) * K + kc * BKK + gchunk * 8);
            cp16(sb + GB_OFF(buf) + (uint32_t)r * (HSTRIDE * 2) + gchunk * 16,
                 B + (size_t)(bn + r) * K + kc * BKK + gchunk * 8);
        }
        asm volatile("cp.async.commit_group;" ::: "memory");
    };

    const int NC = K / BKK;
    loadTile(0, 0);
    loadTile(1, 1);
    loadTile(2, 2);

    for (int c = 0; c < NC; c++) {
        const int b = c & 3;
        asm volatile("cp.async.wait_group 2;" ::: "memory");
        __syncthreads();
        if (c + 3 < NC) loadTile(c + 3, (c + 3) & 3);
        else asm volatile("cp.async.commit_group;" ::: "memory");

        const uint32_t sA = sb + GA_OFF(b);
        const uint32_t sB = sb + GB_OFF(b);
#pragma unroll
        for (int kk = 0; kk < 2; kk++) {
            const uint32_t kb = kk * 32;
            uint32_t af[4][4], bf[8][2];
#pragma unroll
            for (int mt = 0; mt < 4; mt++)
                ldsm4(af[mt], sA + aOff[mt] + kb);
#pragma unroll
            for (int j = 0; j < 4; j++) {
                uint32_t r[4];
                ldsm4(r, sB + bOff[j] + kb);
                bf[2 * j][0] = r[0]; bf[2 * j][1] = r[1];
                bf[2 * j + 1][0] = r[2]; bf[2 * j + 1][1] = r[3];
            }
#pragma unroll
            for (int mt = 0; mt < 4; mt++)
#pragma unroll
                for (int nt = 0; nt < 8; nt++)
                    mma_f16(acc[mt][nt], af[mt], bf[nt]);
        }
    }

    const float scl = (mode & 8) ? 0.125f : 1.0f;
    float2 bv[8];
#pragma unroll
    for (int nt = 0; nt < 8; nt++) {
        int col = bn + wn + nt * 8 + 2 * lc;
        bv[nt] = *(const float2*)(bias + col);
    }
#pragma unroll
    for (int mt = 0; mt < 4; mt++) {
        int row0 = bm + wm + mt * 16 + lr;
#pragma unroll
        for (int nt = 0; nt < 8; nt++) {
            int col = bn + wn + nt * 8 + 2 * lc;
#pragma unroll
            for (int half = 0; half < 2; half++) {
                int row = row0 + half * 8;
                float v0 = acc[mt][nt][2 * half + 0] + bv[nt].x;
                float v1 = acc[mt][nt][2 * half + 1] + bv[nt].y;
                if (mode & 1) { v0 = gelu_f(v0); v1 = gelu_f(v1); }
                v0 *= scl; v1 *= scl;
                if (mode & 2)
                    *(float2*)(C + (size_t)row * N + col) = make_float2(v0, v1);
                if (mode & 4) {
                    __half2 h = __floats2half2_rn(v0, v1);
                    *(__half2*)(H + (size_t)row * N + col) = h;
                }
            }
        }
    }
}

// ---------------------------------------------------------------------------
// fp16 tensor-core causal flash attention, register-resident P (unchanged).
// ---------------------------------------------------------------------------
#define AQH 0
#define AKH 9216
#define AVH 18432
#define AKVBUF 4608
#define ATTH_BYTES (27648 * 2)

__global__ void __launch_bounds__(256, 2) attention_h(
    const __half* __restrict__ Qg, const __half* __restrict__ Kg,
    const __half* __restrict__ Vg, float* __restrict__ Og)
{
    extern __shared__ __half smh[];
    const uint32_t sb = smem_u32(smh);

    const int tid = threadIdx.x;
    const int wid = tid >> 5;
    const int lane = tid & 31;
    const int lr = lane >> 2;
    const int lc = lane & 3;
    const int qt = gridDim.x - 1 - blockIdx.x;
    const int nb = blockIdx.y >> 3;
    const int h  = blockIdx.y & 7;
    const int bm = qt * 128;
    const int wm = wid * 16;

    const size_t base = ((size_t)nb * SEQ) * DMODEL + (size_t)h * DHEAD;

#pragma unroll
    for (int j = 0; j < 4; j++) {
        int c = tid + 256 * j;
        int r = c >> 3;
        int ch = c & 7;
        cp16(sb + (AQH + r * 72 + ch * 8) * 2, Qg + base + (size_t)(bm + r) * DMODEL + ch * 8);
    }
    asm volatile("cp.async.commit_group;" ::: "memory");

    auto loadKV = [&](int kt, int b) {
#pragma unroll
        for (int j = 0; j < 2; j++) {
            int c = tid + 256 * j;
            int r = c >> 3;
            int ch = c & 7;
            size_t g = base + (size_t)(kt * 64 + r) * DMODEL + ch * 8;
            cp16(sb + (AKH + b * AKVBUF + r * 72 + ch * 8) * 2, Kg + g);
            cp16(sb + (AVH + b * AKVBUF + r * 72 + ch * 8) * 2, Vg + g);
        }
        asm volatile("cp.async.commit_group;" ::: "memory");
    };

    loadKV(0, 0);

    asm volatile("cp.async.wait_group 1;" ::: "memory");
    __syncthreads();
    uint32_t qf[4][4];
    {
        uint32_t qOff = sb + (AQH + (uint32_t)(wm + (lane & 15)) * 72) * 2 + ((lane >> 4) << 4);
#pragma unroll
        for (int ks = 0; ks < 4; ks++)
            ldsm4(qf[ks], qOff + ks * 32);
    }

    uint32_t kOff[4];
#pragma unroll
    for (int j = 0; j < 4; j++)
        kOff[j] = (uint32_t)((2 * j + (lane >> 4)) * 8 + (lane & 7)) * 72 + (((lane >> 3) & 1) << 3);
    uint32_t vOff[4];
#pragma unroll
    for (int j = 0; j < 4; j++)
        vOff[j] = (uint32_t)((((lane >> 3) & 1) << 3) + (lane & 7)) * 72 + 16 * j + ((lane >> 4) << 3);

    float of[8][4];
#pragma unroll
    for (int nf = 0; nf < 8; nf++)
#pragma unroll
        for (int t = 0; t < 4; t++) of[nf][t] = 0.0f;
    float m0 = -1e30f, m1 = -1e30f, l0 = 0.0f, l1 = 0.0f;

    const int r0g = bm + wm + lr;
    const int r1g = r0g + 8;
    const int ntiles = qt * 2 + 2;

    for (int kt = 0; kt < ntiles; kt++) {
        const int b = kt & 1;
        asm volatile("cp.async.wait_group 0;" ::: "memory");
        __syncthreads();
        if (kt + 1 < ntiles) loadKV(kt + 1, b ^ 1);

        const uint32_t sK = sb + (AKH + b * AKVBUF) * 2;
        const uint32_t sV = sb + (AVH + b * AKVBUF) * 2;

        float sf[8][4];
#pragma unroll
        for (int nf = 0; nf < 8; nf++)
#pragma unroll
            for (int t = 0; t < 4; t++) sf[nf][t] = 0.0f;
#pragma unroll
        for (int ks = 0; ks < 4; ks++) {
            uint32_t bf[8][2];
#pragma unroll
            for (int j = 0; j < 4; j++) {
                uint32_t r[4];
                ldsm4(r, sK + kOff[j] * 2 + ks * 32);
                bf[2 * j][0] = r[0]; bf[2 * j][1] = r[1];
                bf[2 * j + 1][0] = r[2]; bf[2 * j + 1][1] = r[3];
            }
#pragma unroll
            for (int nf = 0; nf < 8; nf++)
                mma_f16(sf[nf], qf[ks], bf[nf]);
        }

        if (kt >= ntiles - 2) {
#pragma unroll
            for (int nf = 0; nf < 8; nf++) {
                int c0 = kt * 64 + nf * 8 + 2 * lc;
                if (c0     > r0g) sf[nf][0] = -1e30f;
                if (c0 + 1 > r0g) sf[nf][1] = -1e30f;
                if (c0     > r1g) sf[nf][2] = -1e30f;
                if (c0 + 1 > r1g) sf[nf][3] = -1e30f;
            }
        }

        float mx0 = -1e30f, mx1 = -1e30f;
#pragma unroll
        for (int nf = 0; nf < 8; nf++) {
            mx0 = fmaxf(mx0, fmaxf(sf[nf][0], sf[nf][1]));
            mx1 = fmaxf(mx1, fmaxf(sf[nf][2], sf[nf][3]));
        }
        mx0 = fmaxf(mx0, __shfl_xor_sync(0xffffffffu, mx0, 1));
        mx0 = fmaxf(mx0, __shfl_xor_sync(0xffffffffu, mx0, 2));
        mx1 = fmaxf(mx1, __shfl_xor_sync(0xffffffffu, mx1, 1));
        mx1 = fmaxf(mx1, __shfl_xor_sync(0xffffffffu, mx1, 2));
        float mn0 = fmaxf(m0, mx0), mn1 = fmaxf(m1, mx1);
        float corr0 = __expf(m0 - mn0), corr1 = __expf(m1 - mn1);

        float rs0 = 0.0f, rs1 = 0.0f;
        uint32_t pa[4][4];
#pragma unroll
        for (int nf = 0; nf < 8; nf++) {
            float p0 = __expf(sf[nf][0] - mn0);
            float p1 = __expf(sf[nf][1] - mn0);
            float p2 = __expf(sf[nf][2] - mn1);
            float p3 = __expf(sf[nf][3] - mn1);
            rs0 += p0 + p1;
            rs1 += p2 + p3;
            int ks = nf >> 1;
            int hi = (nf & 1) << 1;
            pa[ks][hi + 0] = h2pack(p0, p1);
            pa[ks][hi + 1] = h2pack(p2, p3);
        }
        rs0 += __shfl_xor_sync(0xffffffffu, rs0, 1);
        rs0 += __shfl_xor_sync(0xffffffffu, rs0, 2);
        rs1 += __shfl_xor_sync(0xffffffffu, rs1, 1);
        rs1 += __shfl_xor_sync(0xffffffffu, rs1, 2);
        l0 = l0 * corr0 + rs0;
        l1 = l1 * corr1 + rs1;
        m0 = mn0; m1 = mn1;
#pragma unroll
        for (int nf = 0; nf < 8; nf++) {
            of[nf][0] *= corr0; of[nf][1] *= corr0;
            of[nf][2] *= corr1; of[nf][3] *= corr1;
        }

#pragma unroll
        for (int ks = 0; ks < 4; ks++) {
            uint32_t bf[8][2];
#pragma unroll
            for (int j = 0; j < 4; j++) {
                uint32_t r[4];
                ldsm4t(r, sV + (vOff[j] + (uint32_t)ks * 16 * 72) * 2);
                bf[2 * j][0] = r[0]; bf[2 * j][1] = r[1];
                bf[2 * j + 1][0] = r[2]; bf[2 * j + 1][1] = r[3];
            }
#pragma unroll
            for (int nf = 0; nf < 8; nf++)
                mma_f16(of[nf], pa[ks], bf[nf]);
        }
    }

    const float inv0 = 1.0f / l0;
    const float inv1 = 1.0f / l1;
#pragma unroll
    for (int nf = 0; nf < 8; nf++) {
        int col = nf * 8 + 2 * lc;
        *(float2*)(Og + base + (size_t)r0g * DMODEL + col) =
            make_float2(of[nf][0] * inv0, of[nf][1] * inv0);
        *(float2*)(Og + base + (size_t)r1g * DMODEL + col) =
            make_float2(of[nf][2] * inv1, of[nf][3] * inv1);
    }
}

// ---------------------------------------------------------------------------
extern "C" void kernel_launch(void* const* d_in, const int* in_sizes, int n_in,
                              void* d_out, int out_size) {
    const float* x   = (const float*)d_in[0];
    const float* qW1 = (const float*)d_in[1];
    const float* qb1 = (const float*)d_in[2];
    const float* qW2 = (const float*)d_in[3];
    const float* qb2 = (const float*)d_in[4];
    const float* kW1 = (const float*)d_in[5];
    const float* kb1 = (const float*)d_in[6];
    const float* kW2 = (const float*)d_in[7];
    const float* kb2 = (const float*)d_in[8];
    const float* vW1 = (const float*)d_in[9];
    const float* vb1 = (const float*)d_in[10];
    const float* vW2 = (const float*)d_in[11];
    const float* vb2 = (const float*)d_in[12];

    float* out = (float*)d_out;
    const size_t seg = (size_t)MROWS * DMODEL;
    float* k_out = out;
    float* v_out = out + seg;
    float* o_out = out + 2 * seg;

    __half *ghh, *gxh, *gw1t, *gw2t, *gqh, *gkh, *gvh;
    cudaGetSymbolAddress((void**)&ghh, g_hh);
    cudaGetSymbolAddress((void**)&gxh, g_xh);
    cudaGetSymbolAddress((void**)&gw1t, g_w1t);
    cudaGetSymbolAddress((void**)&gw2t, g_w2t);
    cudaGetSymbolAddress((void**)&gqh, g_qh);
    cudaGetSymbolAddress((void**)&gkh, g_kh);
    cudaGetSymbolAddress((void**)&gvh, g_vh);
    __half* gh0 = ghh;
    __half* gh1 = ghh + (size_t)MROWS * HID;
    __half* gh2 = ghh + 2 * (size_t)MROWS * HID;
    __half* w1t0 = gw1t;
    __half* w1t1 = gw1t + (size_t)HID * DMODEL;
    __half* w1t2 = gw1t + 2 * (size_t)HID * DMODEL;
    __half* w2t0 = gw2t;
    __half* w2t1 = gw2t + (size_t)DMODEL * HID;
    __half* w2t2 = gw2t + 2 * (size_t)DMODEL * HID;

    cudaFuncSetAttribute(gemm_mma, cudaFuncAttributeMaxDynamicSharedMemorySize, SM_BYTES);
    cudaFuncSetAttribute(attention_h, cudaFuncAttributeMaxDynamicSharedMemorySize, ATTH_BYTES);

    // Prepass
    {
        int n4 = (MROWS * DMODEL) / 4;
        cvt_x_kernel<<<(n4 + 255) / 256, 256>>>(x, gxh, n4);
        dim3 tb(32, 8);
        transpose_h<<<dim3(HID / 32, DMODEL / 32, 3), tb>>>(qW1, kW1, vW1, w1t0, w1t1, w1t2, DMODEL, HID);
        transpose_h<<<dim3(DMODEL / 32, HID / 32, 3), tb>>>(qW2, kW2, vW2, w2t0, w2t1, w2t2, HID, DMODEL);
    }

    // Stage 1: hidden[z] = fp16(gelu(x @ W1[z] + b1[z]))  — mode 5 (gelu|fp16)
    {
        dim3 g(HID / BN, MROWS / BM, 3);
        gemm_mma<<<g, 128, SM_BYTES>>>(gxh, gxh, gxh,
                                       w1t0, w1t1, w1t2,
                                       qb1, kb1, vb1,
                                       nullptr, nullptr, nullptr,
                                       gh0, gh1, gh2,
                                       HID, DMODEL, (5) | (5 << 4) | (5 << 8));
    }
    // Stage 2: q: fp16*0.125 (mode 12); k: fp32+fp16 (mode 6); v: gelu fp32+fp16 (mode 7)
    {
        dim3 g(DMODEL / BN, MROWS / BM, 3);
        gemm_mma<<<g, 128, SM_BYTES>>>(gh0, gh1, gh2,
                                       w2t0, w2t1, w2t2,
                                       qb2, kb2, vb2,
                                       nullptr, k_out, v_out,
                                       gqh, gkh, gvh,
                                       DMODEL, HID, (12) | (6 << 4) | (7 << 8));
    }
    // Stage 3: attention (fp16 tensor cores, register-resident P)
    {
        dim3 ga(SEQ / 128, 2 * NHEADS);
        attention_h<<<ga, 256, ATTH_BYTES>>>(gqh, gkh, gvh, o_out);
    }
}

// round 14
// speedup vs baseline: 1.0065x; 1.0065x over previous
#include <cuda_runtime.h>
#include <cuda_fp16.h>
#include <math.h>
#include <stdint.h>

// ---------------------------------------------------------------------------
// Problem: x (2,2048,512); W1 (512,2048); W2 (2048,512); HEADS=8
// M = 4096 rows. Output = concat(k, v, out), each 4096*512 fp32.
// R14: GEMM reverted to R11 (256-thr, 8 warps 64x32, 4-stage ring — best
// measured). Attention: KV ring deepened to 3 buffers, wait_group 1 keeps
// loads in flight across the whole tile compute.
// ---------------------------------------------------------------------------
#define MROWS 4096
#define DMODEL 512
#define HID 2048
#define SEQ 2048
#define NHEADS 8
#define DHEAD 64

#define BM 128
#define BN 128
#define BKK 32
#define HSTRIDE 40      // gemm smem row stride in halves

// Scratch (device globals: allocation-free rule)
__device__ __align__(16) __half g_hh[3][(size_t)MROWS * HID];     // hidden fp16
__device__ __align__(16) __half g_xh[(size_t)MROWS * DMODEL];     // x fp16
__device__ __align__(16) __half g_w1t[3][(size_t)HID * DMODEL];
__device__ __align__(16) __half g_w2t[3][(size_t)DMODEL * HID];
__device__ __align__(16) __half g_qh[(size_t)MROWS * DMODEL];     // q*0.125 fp16
__device__ __align__(16) __half g_kh[(size_t)MROWS * DMODEL];     // k fp16 copy
__device__ __align__(16) __half g_vh[(size_t)MROWS * DMODEL];     // v fp16 copy

// ----------------------------- helpers -------------------------------------
__device__ __forceinline__ uint32_t smem_u32(const void* p) {
    uint32_t a;
    asm("{ .reg .u64 t; cvta.to.shared.u64 t, %1; cvt.u32.u64 %0, t; }" : "=r"(a) : "l"(p));
    return a;
}
__device__ __forceinline__ void cp16(uint32_t saddr, const void* g) {
    asm volatile("cp.async.cg.shared.global [%0], [%1], 16;" :: "r"(saddr), "l"(g));
}
__device__ __forceinline__ float gelu_f(float x) {
    float x3 = x * x * x;
    float t = tanhf(0.7978845608028654f * (x + 0.044715f * x3));
    return 0.5f * x * (1.0f + t);
}
__device__ __forceinline__ void mma_f16(float* c, const uint32_t* a, const uint32_t* b) {
    asm volatile(
        "mma.sync.aligned.m16n8k16.row.col.f32.f16.f16.f32 "
        "{%0,%1,%2,%3}, {%4,%5,%6,%7}, {%8,%9}, {%0,%1,%2,%3};"
        : "+f"(c[0]), "+f"(c[1]), "+f"(c[2]), "+f"(c[3])
        : "r"(a[0]), "r"(a[1]), "r"(a[2]), "r"(a[3]), "r"(b[0]), "r"(b[1]));
}
__device__ __forceinline__ void ldsm4(uint32_t* r, uint32_t addr) {
    asm volatile("ldmatrix.sync.aligned.m8n8.x4.shared.b16 {%0,%1,%2,%3}, [%4];"
        : "=r"(r[0]), "=r"(r[1]), "=r"(r[2]), "=r"(r[3]) : "r"(addr));
}
__device__ __forceinline__ void ldsm4t(uint32_t* r, uint32_t addr) {
    asm volatile("ldmatrix.sync.aligned.m8n8.x4.trans.shared.b16 {%0,%1,%2,%3}, [%4];"
        : "=r"(r[0]), "=r"(r[1]), "=r"(r[2]), "=r"(r[3]) : "r"(addr));
}
__device__ __forceinline__ uint32_t h2pack(float a, float b) {
    __half2 h = __floats2half2_rn(a, b);
    return *(uint32_t*)&h;
}

// ---------------------------------------------------------------------------
// Prepass: convert x to fp16
// ---------------------------------------------------------------------------
__global__ void cvt_x_kernel(const float* __restrict__ in, __half* __restrict__ out, int n4) {
    int i = blockIdx.x * blockDim.x + threadIdx.x;
    if (i < n4) {
        float4 v = ((const float4*)in)[i];
        __half2 h0 = __floats2half2_rn(v.x, v.y);
        __half2 h1 = __floats2half2_rn(v.z, v.w);
        ((uint2*)out)[i] = make_uint2(*(uint32_t*)&h0, *(uint32_t*)&h1);
    }
}

// ---------------------------------------------------------------------------
// Prepass: transpose weights to fp16. src R x C fp32 -> dst C x R fp16.
// ---------------------------------------------------------------------------
__global__ void transpose_h(const float* __restrict__ s0, const float* __restrict__ s1,
                            const float* __restrict__ s2,
                            __half* __restrict__ d0, __half* __restrict__ d1,
                            __half* __restrict__ d2, int R, int C) {
    __shared__ float tile[32][33];
    const int z = blockIdx.z;
    const float* src = (z == 0) ? s0 : (z == 1) ? s1 : s2;
    __half* dst = (z == 0) ? d0 : (z == 1) ? d1 : d2;
    int tx = threadIdx.x, ty = threadIdx.y;
    int bx = blockIdx.x, by = blockIdx.y;
#pragma unroll
    for (int j = 0; j < 4; j++) {
        int r = by * 32 + ty + j * 8;
        int c = bx * 32 + tx;
        tile[ty + j * 8][tx] = src[(size_t)r * C + c];
    }
    __syncthreads();
#pragma unroll
    for (int j = 0; j < 4; j++) {
        int dr = bx * 32 + ty + j * 8;
        int dc = by * 32 + tx;
        dst[(size_t)dr * R + dc] = __float2half_rn(tile[tx][ty + j * 8]);
    }
}

// ---------------------------------------------------------------------------
// fp16 tensor-core GEMM (R11 config): 4-stage ring, 8 warps (2Mx4N, 64x32).
// out = act(A[z] @ Bt[z]^T + b[z])
// mode per z (4 bits): bit0 gelu, bit1 fp32 out, bit2 fp16 out, bit3 *0.125.
// ---------------------------------------------------------------------------
#define GA_OFF(buf) ((buf) * 10240u)
#define GB_OFF(buf) (40960u + (buf) * 10240u)
#define SM_BYTES 81920

__global__ void __launch_bounds__(256, 2) gemm_mma(
    const __half* __restrict__ A0, const __half* __restrict__ A1, const __half* __restrict__ A2,
    const __half* __restrict__ B0, const __half* __restrict__ B1, const __half* __restrict__ B2,
    const float* __restrict__ bias0, const float* __restrict__ bias1, const float* __restrict__ bias2,
    float* __restrict__ C0, float* __restrict__ C1, float* __restrict__ C2,
    __half* __restrict__ H0, __half* __restrict__ H1, __half* __restrict__ H2,
    int N, int K, int actModes)
{
    extern __shared__ char smem[];
    const uint32_t sb = smem_u32(smem);

    const int z = blockIdx.z;
    const __half* A = (z == 0) ? A0 : (z == 1) ? A1 : A2;
    const __half* B = (z == 0) ? B0 : (z == 1) ? B1 : B2;
    const float* bias = (z == 0) ? bias0 : (z == 1) ? bias1 : bias2;
    float* C = (z == 0) ? C0 : (z == 1) ? C1 : C2;
    __half* H = (z == 0) ? H0 : (z == 1) ? H1 : H2;
    const int mode = (actModes >> (4 * z)) & 15;

    const int tid = threadIdx.x;
    const int wid = tid >> 5;
    const int lane = tid & 31;
    const int bm = blockIdx.y * BM;
    const int bn = blockIdx.x * BN;
    const int wm = (wid >> 2) * 64;
    const int wn = (wid & 3) * 32;

    const int lr = lane >> 2;
    const int lc = lane & 3;

    const int grow = tid >> 2;
    const int gchunk = tid & 3;

    uint32_t aOff[4];
#pragma unroll
    for (int mt = 0; mt < 4; mt++)
        aOff[mt] = (uint32_t)(wm + mt * 16 + (lane & 15)) * (HSTRIDE * 2) + ((lane >> 4) << 4);
    uint32_t bOff[2];
#pragma unroll
    for (int j = 0; j < 2; j++)
        bOff[j] = (uint32_t)(wn + (2 * j + (lane >> 4)) * 8 + (lane & 7)) * (HSTRIDE * 2) + (((lane >> 3) & 1) << 4);

    float acc[4][4][4];
#pragma unroll
    for (int i = 0; i < 4; i++)
#pragma unroll
        for (int j = 0; j < 4; j++)
#pragma unroll
            for (int t = 0; t < 4; t++) acc[i][j][t] = 0.0f;

    auto loadTile = [&](int kc, int buf) {
#pragma unroll
        for (int j = 0; j < 2; j++) {
            int r = grow + 64 * j;
            cp16(sb + GA_OFF(buf) + (uint32_t)r * (HSTRIDE * 2) + gchunk * 16,
                 A + (size_t)(bm + r) * K + kc * BKK + gchunk * 8);
            cp16(sb + GB_OFF(buf) + (uint32_t)r * (HSTRIDE * 2) + gchunk * 16,
                 B + (size_t)(bn + r) * K + kc * BKK + gchunk * 8);
        }
        asm volatile("cp.async.commit_group;" ::: "memory");
    };

    const int NC = K / BKK;
    loadTile(0, 0);
    loadTile(1, 1);
    loadTile(2, 2);

    for (int c = 0; c < NC; c++) {
        const int b = c & 3;
        asm volatile("cp.async.wait_group 2;" ::: "memory");
        __syncthreads();
        if (c + 3 < NC) loadTile(c + 3, (c + 3) & 3);
        else asm volatile("cp.async.commit_group;" ::: "memory");

        const uint32_t sA = sb + GA_OFF(b);
        const uint32_t sB = sb + GB_OFF(b);
#pragma unroll
        for (int kk = 0; kk < 2; kk++) {
            const uint32_t kb = kk * 32;
            uint32_t af[4][4], bf[4][2];
#pragma unroll
            for (int mt = 0; mt < 4; mt++)
                ldsm4(af[mt], sA + aOff[mt] + kb);
#pragma unroll
            for (int j = 0; j < 2; j++) {
                uint32_t r[4];
                ldsm4(r, sB + bOff[j] + kb);
                bf[2 * j][0] = r[0]; bf[2 * j][1] = r[1];
                bf[2 * j + 1][0] = r[2]; bf[2 * j + 1][1] = r[3];
            }
#pragma unroll
            for (int mt = 0; mt < 4; mt++)
#pragma unroll
                for (int nt = 0; nt < 4; nt++)
                    mma_f16(acc[mt][nt], af[mt], bf[nt]);
        }
    }

    const float scl = (mode & 8) ? 0.125f : 1.0f;
    float2 bv[4];
#pragma unroll
    for (int nt = 0; nt < 4; nt++) {
        int col = bn + wn + nt * 8 + 2 * lc;
        bv[nt] = *(const float2*)(bias + col);
    }
#pragma unroll
    for (int mt = 0; mt < 4; mt++) {
        int row0 = bm + wm + mt * 16 + lr;
#pragma unroll
        for (int nt = 0; nt < 4; nt++) {
            int col = bn + wn + nt * 8 + 2 * lc;
#pragma unroll
            for (int half = 0; half < 2; half++) {
                int row = row0 + half * 8;
                float v0 = acc[mt][nt][2 * half + 0] + bv[nt].x;
                float v1 = acc[mt][nt][2 * half + 1] + bv[nt].y;
                if (mode & 1) { v0 = gelu_f(v0); v1 = gelu_f(v1); }
                v0 *= scl; v1 *= scl;
                if (mode & 2)
                    *(float2*)(C + (size_t)row * N + col) = make_float2(v0, v1);
                if (mode & 4) {
                    __half2 h = __floats2half2_rn(v0, v1);
                    *(__half2*)(H + (size_t)row * N + col) = h;
                }
            }
        }
    }
}

// ---------------------------------------------------------------------------
// fp16 tensor-core causal flash attention, register-resident P.
// R14: 3-deep KV ring; wait_group 1 keeps one tile's loads in flight across
// the whole compute phase. One __syncthreads per key tile.
// Smem (halves): Q[128*72]=9216 | K[3][64*72]=13824 | V[3][64*72]=13824.
// ---------------------------------------------------------------------------
#define AQH 0
#define AKH 9216
#define AVH 23040
#define AKVBUF 4608
#define ATTH_BYTES (36864 * 2)

__global__ void __launch_bounds__(256, 2) attention_h(
    const __half* __restrict__ Qg, const __half* __restrict__ Kg,
    const __half* __restrict__ Vg, float* __restrict__ Og)
{
    extern __shared__ __half smh[];
    const uint32_t sb = smem_u32(smh);

    const int tid = threadIdx.x;
    const int wid = tid >> 5;
    const int lane = tid & 31;
    const int lr = lane >> 2;
    const int lc = lane & 3;
    const int qt = gridDim.x - 1 - blockIdx.x;   // heavy tiles first
    const int nb = blockIdx.y >> 3;
    const int h  = blockIdx.y & 7;
    const int bm = qt * 128;
    const int wm = wid * 16;

    const size_t base = ((size_t)nb * SEQ) * DMODEL + (size_t)h * DHEAD;

    // Q staging (commit group 0).
#pragma unroll
    for (int j = 0; j < 4; j++) {
        int c = tid + 256 * j;
        int r = c >> 3;
        int ch = c & 7;
        cp16(sb + (AQH + r * 72 + ch * 8) * 2, Qg + base + (size_t)(bm + r) * DMODEL + ch * 8);
    }
    asm volatile("cp.async.commit_group;" ::: "memory");

    auto loadKV = [&](int kt, int b) {
#pragma unroll
        for (int j = 0; j < 2; j++) {
            int c = tid + 256 * j;
            int r = c >> 3;
            int ch = c & 7;
            size_t g = base + (size_t)(kt * 64 + r) * DMODEL + ch * 8;
            cp16(sb + (AKH + b * AKVBUF + r * 72 + ch * 8) * 2, Kg + g);
            cp16(sb + (AVH + b * AKVBUF + r * 72 + ch * 8) * 2, Vg + g);
        }
        asm volatile("cp.async.commit_group;" ::: "memory");
    };

    const int ntiles = qt * 2 + 2;   // always >= 2
    loadKV(0, 0);                    // group 1
    loadKV(1, 1);                    // group 2

    // Wait for Q (2 groups may pend), load Q fragments.
    asm volatile("cp.async.wait_group 2;" ::: "memory");
    __syncthreads();
    uint32_t qf[4][4];
    {
        uint32_t qOff = sb + (AQH + (uint32_t)(wm + (lane & 15)) * 72) * 2 + ((lane >> 4) << 4);
#pragma unroll
        for (int ks = 0; ks < 4; ks++)
            ldsm4(qf[ks], qOff + ks * 32);
    }

    uint32_t kOff[4];
#pragma unroll
    for (int j = 0; j < 4; j++)
        kOff[j] = (uint32_t)((2 * j + (lane >> 4)) * 8 + (lane & 7)) * 72 + (((lane >> 3) & 1) << 3);
    uint32_t vOff[4];
#pragma unroll
    for (int j = 0; j < 4; j++)
        vOff[j] = (uint32_t)((((lane >> 3) & 1) << 3) + (lane & 7)) * 72 + 16 * j + ((lane >> 4) << 3);

    float of[8][4];
#pragma unroll
    for (int nf = 0; nf < 8; nf++)
#pragma unroll
        for (int t = 0; t < 4; t++) of[nf][t] = 0.0f;
    float m0 = -1e30f, m1 = -1e30f, l0 = 0.0f, l1 = 0.0f;

    const int r0g = bm + wm + lr;
    const int r1g = r0g + 8;

    int b = 0;   // ring buffer index for current tile
    for (int kt = 0; kt < ntiles; kt++) {
        // KV_kt complete (KV_{kt+1} may still be in flight).
        asm volatile("cp.async.wait_group 1;" ::: "memory");
        __syncthreads();   // visibility + compute of buffer (kt+2)%3 done (it was tile kt-1's... safe: consumed at kt-1)
        if (kt + 2 < ntiles) {
            int nb3 = b + 2; if (nb3 >= 3) nb3 -= 3;
            loadKV(kt + 2, nb3);
        } else {
            asm volatile("cp.async.commit_group;" ::: "memory");
        }

        const uint32_t sK = sb + (AKH + b * AKVBUF) * 2;
        const uint32_t sV = sb + (AVH + b * AKVBUF) * 2;

        // S = Q K^T
        float sf[8][4];
#pragma unroll
        for (int nf = 0; nf < 8; nf++)
#pragma unroll
            for (int t = 0; t < 4; t++) sf[nf][t] = 0.0f;
#pragma unroll
        for (int ks = 0; ks < 4; ks++) {
            uint32_t bf[8][2];
#pragma unroll
            for (int j = 0; j < 4; j++) {
                uint32_t r[4];
                ldsm4(r, sK + kOff[j] * 2 + ks * 32);
                bf[2 * j][0] = r[0]; bf[2 * j][1] = r[1];
                bf[2 * j + 1][0] = r[2]; bf[2 * j + 1][1] = r[3];
            }
#pragma unroll
            for (int nf = 0; nf < 8; nf++)
                mma_f16(sf[nf], qf[ks], bf[nf]);
        }

        // Causal mask (only last two tiles touch the diagonal)
        if (kt >= ntiles - 2) {
#pragma unroll
            for (int nf = 0; nf < 8; nf++) {
                int c0 = kt * 64 + nf * 8 + 2 * lc;
                if (c0     > r0g) sf[nf][0] = -1e30f;
                if (c0 + 1 > r0g) sf[nf][1] = -1e30f;
                if (c0     > r1g) sf[nf][2] = -1e30f;
                if (c0 + 1 > r1g) sf[nf][3] = -1e30f;
            }
        }

        // Online softmax; P packed straight into A-fragments.
        float mx0 = -1e30f, mx1 = -1e30f;
#pragma unroll
        for (int nf = 0; nf < 8; nf++) {
            mx0 = fmaxf(mx0, fmaxf(sf[nf][0], sf[nf][1]));
            mx1 = fmaxf(mx1, fmaxf(sf[nf][2], sf[nf][3]));
        }
        mx0 = fmaxf(mx0, __shfl_xor_sync(0xffffffffu, mx0, 1));
        mx0 = fmaxf(mx0, __shfl_xor_sync(0xffffffffu, mx0, 2));
        mx1 = fmaxf(mx1, __shfl_xor_sync(0xffffffffu, mx1, 1));
        mx1 = fmaxf(mx1, __shfl_xor_sync(0xffffffffu, mx1, 2));
        float mn0 = fmaxf(m0, mx0), mn1 = fmaxf(m1, mx1);
        float corr0 = __expf(m0 - mn0), corr1 = __expf(m1 - mn1);

        float rs0 = 0.0f, rs1 = 0.0f;
        uint32_t pa[4][4];
#pragma unroll
        for (int nf = 0; nf < 8; nf++) {
            float p0 = __expf(sf[nf][0] - mn0);
            float p1 = __expf(sf[nf][1] - mn0);
            float p2 = __expf(sf[nf][2] - mn1);
            float p3 = __expf(sf[nf][3] - mn1);
            rs0 += p0 + p1;
            rs1 += p2 + p3;
            int ks = nf >> 1;
            int hi = (nf & 1) << 1;
            pa[ks][hi + 0] = h2pack(p0, p1);
            pa[ks][hi + 1] = h2pack(p2, p3);
        }
        rs0 += __shfl_xor_sync(0xffffffffu, rs0, 1);
        rs0 += __shfl_xor_sync(0xffffffffu, rs0, 2);
        rs1 += __shfl_xor_sync(0xffffffffu, rs1, 1);
        rs1 += __shfl_xor_sync(0xffffffffu, rs1, 2);
        l0 = l0 * corr0 + rs0;
        l1 = l1 * corr1 + rs1;
        m0 = mn0; m1 = mn1;
#pragma unroll
        for (int nf = 0; nf < 8; nf++) {
            of[nf][0] *= corr0; of[nf][1] *= corr0;
            of[nf][2] *= corr1; of[nf][3] *= corr1;
        }

        // O += P V
#pragma unroll
        for (int ks = 0; ks < 4; ks++) {
            uint32_t bf[8][2];
#pragma unroll
            for (int j = 0; j < 4; j++) {
                uint32_t r[4];
                ldsm4t(r, sV + (vOff[j] + (uint32_t)ks * 16 * 72) * 2);
                bf[2 * j][0] = r[0]; bf[2 * j][1] = r[1];
                bf[2 * j + 1][0] = r[2]; bf[2 * j + 1][1] = r[3];
            }
#pragma unroll
            for (int nf = 0; nf < 8; nf++)
                mma_f16(of[nf], pa[ks], bf[nf]);
        }

        if (++b == 3) b = 0;
    }

    const float inv0 = 1.0f / l0;
    const float inv1 = 1.0f / l1;
#pragma unroll
    for (int nf = 0; nf < 8; nf++) {
        int col = nf * 8 + 2 * lc;
        *(float2*)(Og + base + (size_t)r0g * DMODEL + col) =
            make_float2(of[nf][0] * inv0, of[nf][1] * inv0);
        *(float2*)(Og + base + (size_t)r1g * DMODEL + col) =
            make_float2(of[nf][2] * inv1, of[nf][3] * inv1);
    }
}

// ---------------------------------------------------------------------------
extern "C" void kernel_launch(void* const* d_in, const int* in_sizes, int n_in,
                              void* d_out, int out_size) {
    const float* x   = (const float*)d_in[0];
    const float* qW1 = (const float*)d_in[1];
    const float* qb1 = (const float*)d_in[2];
    const float* qW2 = (const float*)d_in[3];
    const float* qb2 = (const float*)d_in[4];
    const float* kW1 = (const float*)d_in[5];
    const float* kb1 = (const float*)d_in[6];
    const float* kW2 = (const float*)d_in[7];
    const float* kb2 = (const float*)d_in[8];
    const float* vW1 = (const float*)d_in[9];
    const float* vb1 = (const float*)d_in[10];
    const float* vW2 = (const float*)d_in[11];
    const float* vb2 = (const float*)d_in[12];

    float* out = (float*)d_out;
    const size_t seg = (size_t)MROWS * DMODEL;
    float* k_out = out;
    float* v_out = out + seg;
    float* o_out = out + 2 * seg;

    __half *ghh, *gxh, *gw1t, *gw2t, *gqh, *gkh, *gvh;
    cudaGetSymbolAddress((void**)&ghh, g_hh);
    cudaGetSymbolAddress((void**)&gxh, g_xh);
    cudaGetSymbolAddress((void**)&gw1t, g_w1t);
    cudaGetSymbolAddress((void**)&gw2t, g_w2t);
    cudaGetSymbolAddress((void**)&gqh, g_qh);
    cudaGetSymbolAddress((void**)&gkh, g_kh);
    cudaGetSymbolAddress((void**)&gvh, g_vh);
    __half* gh0 = ghh;
    __half* gh1 = ghh + (size_t)MROWS * HID;
    __half* gh2 = ghh + 2 * (size_t)MROWS * HID;
    __half* w1t0 = gw1t;
    __half* w1t1 = gw1t + (size_t)HID * DMODEL;
    __half* w1t2 = gw1t + 2 * (size_t)HID * DMODEL;
    __half* w2t0 = gw2t;
    __half* w2t1 = gw2t + (size_t)DMODEL * HID;
    __half* w2t2 = gw2t + 2 * (size_t)DMODEL * HID;

    cudaFuncSetAttribute(gemm_mma, cudaFuncAttributeMaxDynamicSharedMemorySize, SM_BYTES);
    cudaFuncSetAttribute(attention_h, cudaFuncAttributeMaxDynamicSharedMemorySize, ATTH_BYTES);

    // Prepass
    {
        int n4 = (MROWS * DMODEL) / 4;
        cvt_x_kernel<<<(n4 + 255) / 256, 256>>>(x, gxh, n4);
        dim3 tb(32, 8);
        transpose_h<<<dim3(HID / 32, DMODEL / 32, 3), tb>>>(qW1, kW1, vW1, w1t0, w1t1, w1t2, DMODEL, HID);
        transpose_h<<<dim3(DMODEL / 32, HID / 32, 3), tb>>>(qW2, kW2, vW2, w2t0, w2t1, w2t2, HID, DMODEL);
    }

    // Stage 1: hidden[z] = fp16(gelu(x @ W1[z] + b1[z]))  — mode 5 (gelu|fp16)
    {
        dim3 g(HID / BN, MROWS / BM, 3);
        gemm_mma<<<g, 256, SM_BYTES>>>(gxh, gxh, gxh,
                                       w1t0, w1t1, w1t2,
                                       qb1, kb1, vb1,
                                       nullptr, nullptr, nullptr,
                                       gh0, gh1, gh2,
                                       HID, DMODEL, (5) | (5 << 4) | (5 << 8));
    }
    // Stage 2: q: fp16*0.125 (mode 12); k: fp32+fp16 (mode 6); v: gelu fp32+fp16 (mode 7)
    {
        dim3 g(DMODEL / BN, MROWS / BM, 3);
        gemm_mma<<<g, 256, SM_BYTES>>>(gh0, gh1, gh2,
                                       w2t0, w2t1, w2t2,
                                       qb2, kb2, vb2,
                                       nullptr, k_out, v_out,
                                       gqh, gkh, gvh,
                                       DMODEL, HID, (12) | (6 << 4) | (7 << 8));
    }
    // Stage 3: attention (fp16 tensor cores, 3-deep KV ring)
    {
        dim3 ga(SEQ / 128, 2 * NHEADS);
        attention_h<<<ga, 256, ATTH_BYTES>>>(gqh, gkh, gvh, o_out);
    }
}